// round 11
// baseline (speedup 1.0000x reference)
#include <cuda_runtime.h>
#include <cuda_bf16.h>
#include <cstdint>
#include <cstddef>

#define B_DIM    4096
#define IN_DIM   3136
#define FEAT_DIM 6272
#define OUT_DIM  500
#define WL1_CAP  (1 << 20)
#define WL2_CAP  (1 << 17)

// ---------------- static device scratch (allocation-free) ----------------
__device__ int8_t g_xq [(size_t)B_DIM * IN_DIM];            // x as s8 {0,1}
__device__ int8_t g_s1q[(size_t)B_DIM * FEAT_DIM];          // hidden spikes s8 {0,1}
__device__ int8_t g_w1q[3ull * FEAT_DIM * IN_DIM];          // W1 limbs q0/q1/q2
__device__ int8_t g_w2q[3ull * 512 * FEAT_DIM];             // W2 limbs (rows padded 512)
__device__ float  g_cs1[FEAT_DIM];                          // per-col scale (pow2)
__device__ float  g_cb1[FEAT_DIM];                          // per-col residual bound
__device__ float  g_cs2[512];
__device__ float  g_cb2[512];
__device__ int    g_cnt[2];
__device__ unsigned g_list1[WL1_CAP];
__device__ unsigned g_list2[WL2_CAP];

// epilogue combine constants (exact powers of 2)
#define C0 0.015625f            // 2^-6
#define C1 1.220703125e-4f      // 2^-13
#define C2 9.5367431640625e-7f  // 2^-20

// ---------------- PTX helpers ----------------
__device__ __forceinline__ uint32_t smem_u32(const void* p) {
    uint32_t a;
    asm("{ .reg .u64 t; cvta.to.shared.u64 t, %1; cvt.u32.u64 %0, t; }" : "=r"(a) : "l"(p));
    return a;
}
__device__ __forceinline__ void cp_async16(uint32_t dst, const void* src, int src_bytes) {
    asm volatile("cp.async.cg.shared.global [%0], [%1], 16, %2;"
                 :: "r"(dst), "l"(src), "r"(src_bytes) : "memory");
}
__device__ __forceinline__ void cp_commit() {
    asm volatile("cp.async.commit_group;" ::: "memory");
}
template <int N>
__device__ __forceinline__ void cp_wait() {
    asm volatile("cp.async.wait_group %0;" :: "n"(N) : "memory");
}
__device__ __forceinline__ void ldm_x4(uint32_t* r, uint32_t a) {
    asm volatile("ldmatrix.sync.aligned.m8n8.x4.shared.b16 {%0,%1,%2,%3}, [%4];"
                 : "=r"(r[0]), "=r"(r[1]), "=r"(r[2]), "=r"(r[3]) : "r"(a));
}
// s8 MMA, 16x8x32, s32 accumulate. Byte layout of frags matches the bf16
// m16n8k16 pattern (reg = 4 consecutive k-bytes), so ldmatrix use is identical.
__device__ __forceinline__ void mma_s8(int* c, const uint32_t* a, uint32_t b0, uint32_t b1) {
    asm volatile(
        "mma.sync.aligned.m16n8k32.row.col.s32.s8.s8.s32 "
        "{%0,%1,%2,%3}, {%4,%5,%6,%7}, {%8,%9}, {%0,%1,%2,%3};"
        : "+r"(c[0]), "+r"(c[1]), "+r"(c[2]), "+r"(c[3])
        : "r"(a[0]), "r"(a[1]), "r"(a[2]), "r"(a[3]), "r"(b0), "r"(b1));
}

// ---------------- converter kernels ----------------
__global__ void conv_s8_kernel(const float4* __restrict__ in, char4* __restrict__ out, int n4) {
    int i = blockIdx.x * blockDim.x + threadIdx.x;
    if (i < n4) {
        float4 v = in[i];
        out[i] = make_char4(v.x != 0.0f, v.y != 0.0f, v.z != 0.0f, v.w != 0.0f);
    }
}

// 3-limb s8 quantization, one warp per weight row (= GEMM output column):
//   w = s*(q0*2^-6 + q1*2^-13 + q2*2^-20) + res,  s = pow2 >= max|w_row|
//   cb[j] = sum |res| (inflated), cs[j] = s
__global__ void quant3_kernel(const float* __restrict__ W, int8_t* __restrict__ q,
                              size_t limbStride, float* __restrict__ cs,
                              float* __restrict__ cb, int K, int rows) {
    const int j = blockIdx.x * (blockDim.x >> 5) + (threadIdx.x >> 5);
    if (j >= rows) return;
    const int lane = threadIdx.x & 31;
    const float* wr = W + (size_t)j * K;

    float mx = 0.0f;
    for (int i = lane; i < K; i += 32) mx = fmaxf(mx, fabsf(wr[i]));
#pragma unroll
    for (int o = 16; o; o >>= 1) mx = fmaxf(mx, __shfl_xor_sync(0xFFFFFFFFu, mx, o));
    float s = 1.0f;
    while (s < mx) s *= 2.0f;
    while (s * 0.5f >= mx) s *= 0.5f;     // mx > 0 for gaussian weights
    const float inv = 1.0f / s;           // exact (pow2)

    float res = 0.0f;
    for (int i = lane; i < K; i += 32) {
        float m  = wr[i] * inv;
        float q0 = rintf(m * 64.0f);
        float r1 = m - q0 * C0;
        float q1 = rintf(r1 * 8192.0f);
        float r2 = r1 - q1 * C1;
        float q2 = rintf(r2 * 1048576.0f);
        float r3 = r2 - q2 * C2;
        res += fabsf(r3);
        q[(size_t)j * K + i]                  = (int8_t)q0;
        q[limbStride + (size_t)j * K + i]     = (int8_t)q1;
        q[2 * limbStride + (size_t)j * K + i] = (int8_t)q2;
    }
#pragma unroll
    for (int o = 16; o; o >>= 1) res += __shfl_xor_sync(0xFFFFFFFFu, res, o);
    if (lane == 0) { cb[j] = res * s * 1.0001f + 1e-6f; cs[j] = s; }
}

// exact fp32 recompute of ambiguous v1 elements -> rewrite s1 spike (s8)
__global__ void fixup1_kernel(const float* __restrict__ x, const float* __restrict__ W1,
                              int8_t* __restrict__ s1q) {
    const int warp = (blockIdx.x * blockDim.x + threadIdx.x) >> 5;
    const int lane = threadIdx.x & 31;
    const int nwarp = (gridDim.x * blockDim.x) >> 5;
    int cnt = g_cnt[0]; if (cnt > WL1_CAP) cnt = WL1_CAP;
    for (int w = warp; w < cnt; w += nwarp) {
        const unsigned idx = g_list1[w];
        const int b = idx / FEAT_DIM, j = idx % FEAT_DIM;
        const float* xr = x  + (size_t)b * IN_DIM;
        const float* wr = W1 + (size_t)j * IN_DIM;
        float s = 0.0f;
        for (int i = lane; i < IN_DIM; i += 32) s = fmaf(xr[i], wr[i], s);
#pragma unroll
        for (int o = 16; o; o >>= 1) s += __shfl_xor_sync(0xFFFFFFFFu, s, o);
        if (lane == 0) s1q[(size_t)b * FEAT_DIM + j] = (s >= 1.0f) ? 1 : 0;
    }
}

// exact fp32 recompute of ambiguous v2 elements -> rewrite output spike
__global__ void fixup2_kernel(const int8_t* __restrict__ s1q,
                              const float* __restrict__ W2, float* __restrict__ out) {
    const int warp = (blockIdx.x * blockDim.x + threadIdx.x) >> 5;
    const int lane = threadIdx.x & 31;
    const int nwarp = (gridDim.x * blockDim.x) >> 5;
    int cnt = g_cnt[1]; if (cnt > WL2_CAP) cnt = WL2_CAP;
    for (int w = warp; w < cnt; w += nwarp) {
        const unsigned idx = g_list2[w];
        const int b = idx / OUT_DIM, j = idx % OUT_DIM;
        const int8_t* sr = s1q + (size_t)b * FEAT_DIM;
        const float* wr = W2 + (size_t)j * FEAT_DIM;
        float s = 0.0f;
        for (int i = lane; i < FEAT_DIM; i += 32)
            if (sr[i]) s += wr[i];
#pragma unroll
        for (int o = 16; o; o >>= 1) s += __shfl_xor_sync(0xFFFFFFFFu, s, o);
        if (lane == 0) out[(size_t)b * OUT_DIM + j] = (s >= 1.0f) ? 1.0f : 0.0f;
    }
}

// ---------------- fused s8 tensor-core spike GEMM ----------------
//  C[M,Nout] = step( A[M,K] @ W[Nout,K]^T ),  W as 3 s8 limbs with separate
//  s32 accumulators, combined in the epilogue with exact pow2 scales.
//  CTA tile 128x64, BK=64 bytes. 256 threads = 8 warps (4m x 2n), warp 32x32.
//  Smem rows 64B, xor-swizzled; stage = A 8KB + 3x4KB B = 20KB.
#define STAGES 4
#define STAGE_BYTES 20480

template <bool OUT_S8, int WL>
__global__ __launch_bounds__(256)
void spike_imma_gemm(const int8_t* __restrict__ A,
                     const int8_t* __restrict__ Wq, size_t limbStride,
                     const float* __restrict__ cs, const float* __restrict__ cb,
                     void* __restrict__ Cout, int K, int Nout)
{
    extern __shared__ char smem[];
    const int tid  = threadIdx.x;
    const int lane = tid & 31;
    const int wid  = tid >> 5;
    const int wm   = wid & 3;       // warp row (32 rows)
    const int wn   = wid >> 2;      // warp col (32 cols)
    const int rowBase = blockIdx.x * 128;   // M-fast grid: W slab stays in L2
    const int colBase = blockIdx.y * 64;

    const int rL  = lane & 15;
    const int ccL = lane >> 4;

    int acc[3][2][4][4];            // [limb][mt][n8-tile][frag]
#pragma unroll
    for (int l = 0; l < 3; l++)
#pragma unroll
        for (int i = 0; i < 2; i++)
#pragma unroll
            for (int j = 0; j < 4; j++)
#pragma unroll
                for (int k = 0; k < 4; k++) acc[l][i][j][k] = 0;

    const uint32_t smem_base = smem_u32(smem);
    const int ITERS = K / 64;

    auto load_stage = [&](int it) {
        const int s  = it % STAGES;
        const int kt = it * 64;
        const uint32_t stA = smem_base + s * STAGE_BYTES;
        const uint32_t stB = stA + 8192;
        // A: 128 rows x 64B = 512 chunks of 16B
#pragma unroll
        for (int i = 0; i < 2; i++) {
            const int idx = tid + i * 256;
            const int r = idx >> 2, c = idx & 3;
            const uint32_t d = stA + r * 64 + (((c ^ (r & 3)) << 4));
            cp_async16(d, A + (size_t)(rowBase + r) * K + kt + c * 16, 16);
        }
        // B: 3 limbs x 64 rows x 64B = 768 chunks
#pragma unroll
        for (int j = 0; j < 3; j++) {
            const int idx = tid + j * 256;
            const int limb = idx >> 8, rem = idx & 255;
            const int r = rem >> 2, c = rem & 3;
            const int gn = colBase + r;
            const int ok = (gn < Nout);
            const int gns = ok ? gn : (Nout - 1);
            const uint32_t d = stB + limb * 4096 + r * 64 + (((c ^ (r & 3)) << 4));
            cp_async16(d, Wq + (size_t)limb * limbStride + (size_t)gns * K + kt + c * 16,
                       ok ? 16 : 0);
        }
        cp_commit();
    };

    load_stage(0);
    load_stage(1);
    load_stage(2);

    for (int it = 0; it < ITERS; ++it) {
        cp_wait<2>();
        __syncthreads();
        if (it + 3 < ITERS) load_stage(it + 3);

        const int s = it % STAGES;
        const uint32_t stA = smem_base + s * STAGE_BYTES;
        const uint32_t stB = stA + 8192;

#pragma unroll
        for (int ks = 0; ks < 2; ks++) {    // two k32 steps per 64B row
            uint32_t afr[2][4];
#pragma unroll
            for (int mt = 0; mt < 2; mt++) {
                const int row = wm * 32 + mt * 16 + rL;
                const uint32_t ad = stA + row * 64 + (((ccL + 2 * ks) ^ (row & 3)) << 4);
                ldm_x4(afr[mt], ad);
            }
#pragma unroll
            for (int limb = 0; limb < 3; limb++) {
                uint32_t bfr[2][4];
#pragma unroll
                for (int nb = 0; nb < 2; nb++) {
                    const int row = wn * 32 + nb * 16 + rL;
                    const uint32_t bd = stB + limb * 4096 + row * 64 +
                                        (((ccL + 2 * ks) ^ (row & 3)) << 4);
                    ldm_x4(bfr[nb], bd);
                }
#pragma unroll
                for (int mt = 0; mt < 2; mt++)
#pragma unroll
                    for (int nb = 0; nb < 2; nb++) {
                        mma_s8(acc[limb][mt][nb * 2 + 0], afr[mt], bfr[nb][0], bfr[nb][2]);
                        mma_s8(acc[limb][mt][nb * 2 + 1], afr[mt], bfr[nb][1], bfr[nb][3]);
                    }
            }
        }
    }

    // ---- epilogue: combine limbs, threshold, store (+ worklist) ----
    const int g = lane >> 2;
    const int t = lane & 3;
#pragma unroll
    for (int mt = 0; mt < 2; mt++) {
#pragma unroll
        for (int nt = 0; nt < 4; nt++) {
            const int row = rowBase + wm * 32 + mt * 16 + g;
            const int col = colBase + wn * 32 + nt * 8 + 2 * t;
            if (col >= Nout) continue;
            const int* a0 = acc[0][mt][nt];
            const int* a1 = acc[1][mt][nt];
            const int* a2 = acc[2][mt][nt];
            const float s0 = cs[col], s1c = cs[col + 1];
            float v[4];
#pragma unroll
            for (int k = 0; k < 4; k++)
                v[k] = ((float)a0[k] * C0 + (float)a1[k] * C1 + (float)a2[k] * C2);
            v[0] *= s0; v[1] *= s1c; v[2] *= s0; v[3] *= s1c;

            if (WL != 0) {
                const float b0 = cb[col]     + 3e-5f;
                const float b1 = cb[col + 1] + 3e-5f;
                const unsigned base0 = (unsigned)row * (unsigned)Nout + col;
                const unsigned base1 = (unsigned)(row + 8) * (unsigned)Nout + col;
                int* cntp = &g_cnt[WL - 1];
                unsigned* listp = (WL == 1) ? g_list1 : g_list2;
                const int cap = (WL == 1) ? WL1_CAP : WL2_CAP;
                if (fabsf(v[0] - 1.0f) < b0) { int p = atomicAdd(cntp, 1); if (p < cap) listp[p] = base0; }
                if (fabsf(v[1] - 1.0f) < b1) { int p = atomicAdd(cntp, 1); if (p < cap) listp[p] = base0 + 1; }
                if (fabsf(v[2] - 1.0f) < b0) { int p = atomicAdd(cntp, 1); if (p < cap) listp[p] = base1; }
                if (fabsf(v[3] - 1.0f) < b1) { int p = atomicAdd(cntp, 1); if (p < cap) listp[p] = base1 + 1; }
            }
            if (OUT_S8) {
                int8_t* o = (int8_t*)Cout;
                *reinterpret_cast<char2*>(o + (size_t)row * Nout + col) =
                    make_char2(v[0] >= 1.0f, v[1] >= 1.0f);
                *reinterpret_cast<char2*>(o + (size_t)(row + 8) * Nout + col) =
                    make_char2(v[2] >= 1.0f, v[3] >= 1.0f);
            } else {
                float* o = (float*)Cout;
                *reinterpret_cast<float2*>(o + (size_t)row * Nout + col) =
                    make_float2(v[0] >= 1.0f ? 1.0f : 0.0f, v[1] >= 1.0f ? 1.0f : 0.0f);
                *reinterpret_cast<float2*>(o + (size_t)(row + 8) * Nout + col) =
                    make_float2(v[2] >= 1.0f ? 1.0f : 0.0f, v[3] >= 1.0f ? 1.0f : 0.0f);
            }
        }
    }
}

// ---------------- host launcher ----------------
extern "C" void kernel_launch(void* const* d_in, const int* in_sizes, int n_in,
                              void* d_out, int out_size)
{
    const float* x  = (const float*)d_in[0];  // [4096, 3136] binary
    const float* W1 = (const float*)d_in[1];  // [6272, 3136]
    const float* W2 = (const float*)d_in[2];  // [500, 6272]
    float* out = (float*)d_out;               // [4096, 500]

    int8_t *xq, *s1q, *w1q, *w2q;
    float *cs1, *cb1, *cs2, *cb2; int* cnt;
    cudaGetSymbolAddress((void**)&xq,  g_xq);
    cudaGetSymbolAddress((void**)&s1q, g_s1q);
    cudaGetSymbolAddress((void**)&w1q, g_w1q);
    cudaGetSymbolAddress((void**)&w2q, g_w2q);
    cudaGetSymbolAddress((void**)&cs1, g_cs1);
    cudaGetSymbolAddress((void**)&cb1, g_cb1);
    cudaGetSymbolAddress((void**)&cs2, g_cs2);
    cudaGetSymbolAddress((void**)&cb2, g_cb2);
    cudaGetSymbolAddress((void**)&cnt, g_cnt);

    cudaMemsetAsync(cnt, 0, 2 * sizeof(int));

    // converters
    {
        int n4 = (B_DIM * IN_DIM) / 4;
        conv_s8_kernel<<<(n4 + 255) / 256, 256>>>((const float4*)x, (char4*)xq, n4);
    }
    quant3_kernel<<<FEAT_DIM / 8, 256>>>(W1, w1q, (size_t)FEAT_DIM * IN_DIM,
                                         cs1, cb1, IN_DIM, FEAT_DIM);
    quant3_kernel<<<(OUT_DIM + 7) / 8, 256>>>(W2, w2q, (size_t)512 * FEAT_DIM,
                                              cs2, cb2, FEAT_DIM, OUT_DIM);

    constexpr int SMEM = STAGES * STAGE_BYTES;   // 80 KB

    // GEMM1: s1 = step(x @ W1^T)  [4096 x 6272]
    {
        cudaFuncSetAttribute(spike_imma_gemm<true, 1>,
                             cudaFuncAttributeMaxDynamicSharedMemorySize, SMEM);
        dim3 grid(B_DIM / 128, FEAT_DIM / 64);       // (32, 98) M-fast
        spike_imma_gemm<true, 1><<<grid, 256, SMEM>>>(
            xq, w1q, (size_t)FEAT_DIM * IN_DIM, cs1, cb1, (void*)s1q, IN_DIM, FEAT_DIM);
    }
    fixup1_kernel<<<256, 256>>>(x, W1, s1q);

    // GEMM2: out = step(s1 @ W2^T)  [4096 x 500]
    {
        cudaFuncSetAttribute(spike_imma_gemm<false, 2>,
                             cudaFuncAttributeMaxDynamicSharedMemorySize, SMEM);
        dim3 grid(B_DIM / 128, (OUT_DIM + 63) / 64); // (32, 8)
        spike_imma_gemm<false, 2><<<grid, 256, SMEM>>>(
            s1q, w2q, (size_t)512 * FEAT_DIM, cs2, cb2, (void*)out, FEAT_DIM, OUT_DIM);
    }
    fixup2_kernel<<<64, 256>>>(s1q, W2, out);
}

// round 13
// speedup vs baseline: 2.9382x; 2.9382x over previous
#include <cuda_runtime.h>
#include <cuda_bf16.h>
#include <cstdint>
#include <cstddef>

#define B_DIM    4096
#define IN_DIM   3136
#define FEAT_DIM 6272
#define OUT_DIM  500
#define WL1_CAP  (1 << 20)
#define WL2_CAP  (1 << 17)

// ---------------- static device scratch (allocation-free) ----------------
__device__ __nv_bfloat16 g_xb [(size_t)B_DIM * IN_DIM];     // x as bf16 (exact)
__device__ __nv_bfloat16 g_s1b[(size_t)B_DIM * FEAT_DIM];   // hidden spikes bf16 (exact)
__device__ __nv_bfloat16 g_w1l[2ull * FEAT_DIM * IN_DIM];   // W1 limbs hi/mid
__device__ __nv_bfloat16 g_w2l[2ull * OUT_DIM * FEAT_DIM];  // W2 limbs hi/mid
__device__ float         g_cb1[FEAT_DIM];                   // per-col residual bound L1
__device__ float         g_cb2[512];                        // per-col residual bound L2
__device__ int           g_cnt[2];                          // worklist counters
__device__ unsigned      g_list1[WL1_CAP];                  // ambiguous v1 elements
__device__ unsigned      g_list2[WL2_CAP];                  // ambiguous v2 elements

// ---------------- PTX helpers ----------------
__device__ __forceinline__ uint32_t smem_u32(const void* p) {
    uint32_t a;
    asm("{ .reg .u64 t; cvta.to.shared.u64 t, %1; cvt.u32.u64 %0, t; }" : "=r"(a) : "l"(p));
    return a;
}
__device__ __forceinline__ void cp_async16(uint32_t dst, const void* src, int src_bytes) {
    asm volatile("cp.async.cg.shared.global [%0], [%1], 16, %2;"
                 :: "r"(dst), "l"(src), "r"(src_bytes) : "memory");
}
__device__ __forceinline__ void cp_commit() {
    asm volatile("cp.async.commit_group;" ::: "memory");
}
template <int N>
__device__ __forceinline__ void cp_wait() {
    asm volatile("cp.async.wait_group %0;" :: "n"(N) : "memory");
}
__device__ __forceinline__ void ldm_x4(uint32_t* r, uint32_t a) {
    asm volatile("ldmatrix.sync.aligned.m8n8.x4.shared.b16 {%0,%1,%2,%3}, [%4];"
                 : "=r"(r[0]), "=r"(r[1]), "=r"(r[2]), "=r"(r[3]) : "r"(a));
}
__device__ __forceinline__ void mma_bf16(float* c, const uint32_t* a, uint32_t b0, uint32_t b1) {
    asm volatile(
        "mma.sync.aligned.m16n8k16.row.col.f32.bf16.bf16.f32 "
        "{%0,%1,%2,%3}, {%4,%5,%6,%7}, {%8,%9}, {%0,%1,%2,%3};"
        : "+f"(c[0]), "+f"(c[1]), "+f"(c[2]), "+f"(c[3])
        : "r"(a[0]), "r"(a[1]), "r"(a[2]), "r"(a[3]), "r"(b0), "r"(b1));
}

// ---------------- converter kernels ----------------
__global__ void conv_bf16_kernel(const float4* __restrict__ in,
                                 __nv_bfloat162* __restrict__ out, int n4) {
    int i = blockIdx.x * blockDim.x + threadIdx.x;
    if (i < n4) {
        float4 v = in[i];
        out[i * 2 + 0] = __nv_bfloat162(__float2bfloat16_rn(v.x), __float2bfloat16_rn(v.y));
        out[i * 2 + 1] = __nv_bfloat162(__float2bfloat16_rn(v.z), __float2bfloat16_rn(v.w));
    }
}

// 2-limb split (hi+mid) fused with per-row residual-bound accumulation
__global__ void split2_cb_kernel(const float4* __restrict__ in,
                                 __nv_bfloat16* __restrict__ limbs,
                                 float* __restrict__ cb,
                                 size_t n, int n4, int K) {
    int i = blockIdx.x * blockDim.x + threadIdx.x;
    if (i >= n4) return;
    float4 v = in[i];
    float w[4] = {v.x, v.y, v.z, v.w};
    __nv_bfloat16 hi[4], mi[4];
    float rsum = 0.0f;
#pragma unroll
    for (int j = 0; j < 4; j++) {
        float f = w[j];
        hi[j] = __float2bfloat16_rn(f);
        float r1 = f - __bfloat162float(hi[j]);
        mi[j] = __float2bfloat16_rn(r1);
        rsum += fabsf(r1 - __bfloat162float(mi[j]));
    }
    __nv_bfloat162* o0 = reinterpret_cast<__nv_bfloat162*>(limbs);
    __nv_bfloat162* o1 = reinterpret_cast<__nv_bfloat162*>(limbs + n);
    o0[i * 2 + 0] = __nv_bfloat162(hi[0], hi[1]); o0[i * 2 + 1] = __nv_bfloat162(hi[2], hi[3]);
    o1[i * 2 + 0] = __nv_bfloat162(mi[0], mi[1]); o1[i * 2 + 1] = __nv_bfloat162(mi[2], mi[3]);

    const int row = (int)(((size_t)i * 4) / (size_t)K);
    const int first = __shfl_sync(0xFFFFFFFFu, row, 0);
    const int last  = __shfl_sync(0xFFFFFFFFu, row, 31);
    if (first == last) {
        float s = rsum;
#pragma unroll
        for (int o = 16; o; o >>= 1) s += __shfl_xor_sync(0xFFFFFFFFu, s, o);
        if ((threadIdx.x & 31) == 0) atomicAdd(&cb[row], s);
    } else {
        atomicAdd(&cb[row], rsum);
    }
}

// exact fp32 recompute of ambiguous v1 elements -> rewrite s1 spike
__global__ void fixup1_kernel(const float* __restrict__ x, const float* __restrict__ W1,
                              __nv_bfloat16* __restrict__ s1b) {
    const int warp = (blockIdx.x * blockDim.x + threadIdx.x) >> 5;
    const int lane = threadIdx.x & 31;
    const int nwarp = (gridDim.x * blockDim.x) >> 5;
    int cnt = g_cnt[0]; if (cnt > WL1_CAP) cnt = WL1_CAP;
    for (int w = warp; w < cnt; w += nwarp) {
        const unsigned idx = g_list1[w];
        const int b = idx / FEAT_DIM, j = idx % FEAT_DIM;
        const float* xr = x  + (size_t)b * IN_DIM;
        const float* wr = W1 + (size_t)j * IN_DIM;
        float s = 0.0f;
        for (int i = lane; i < IN_DIM; i += 32) s = fmaf(xr[i], wr[i], s);
#pragma unroll
        for (int o = 16; o; o >>= 1) s += __shfl_xor_sync(0xFFFFFFFFu, s, o);
        if (lane == 0)
            s1b[(size_t)b * FEAT_DIM + j] = __float2bfloat16(s >= 1.0f ? 1.0f : 0.0f);
    }
}

// exact fp32 recompute of ambiguous v2 elements -> rewrite output spike
__global__ void fixup2_kernel(const __nv_bfloat16* __restrict__ s1b,
                              const float* __restrict__ W2, float* __restrict__ out) {
    const int warp = (blockIdx.x * blockDim.x + threadIdx.x) >> 5;
    const int lane = threadIdx.x & 31;
    const int nwarp = (gridDim.x * blockDim.x) >> 5;
    int cnt = g_cnt[1]; if (cnt > WL2_CAP) cnt = WL2_CAP;
    for (int w = warp; w < cnt; w += nwarp) {
        const unsigned idx = g_list2[w];
        const int b = idx / OUT_DIM, j = idx % OUT_DIM;
        const __nv_bfloat16* sr = s1b + (size_t)b * FEAT_DIM;
        const float* wr = W2 + (size_t)j * FEAT_DIM;
        float s = 0.0f;
        for (int i = lane; i < FEAT_DIM; i += 32)
            s = fmaf(__bfloat162float(sr[i]), wr[i], s);
#pragma unroll
        for (int o = 16; o; o >>= 1) s += __shfl_xor_sync(0xFFFFFFFFu, s, o);
        if (lane == 0)
            out[(size_t)b * OUT_DIM + j] = (s >= 1.0f) ? 1.0f : 0.0f;
    }
}

// ---------------- fused bf16 mma.sync spike GEMM (imma-clone structure) ----
//  C[M,Nout] = step( A[M,K] @ W[Nout,K]^T ), W as 2 bf16 limbs with SEPARATE
//  fp32 accumulator sets (combined in the epilogue with one fp32 add).
//  CTA tile 128x64, BK=32 (64B rows), 256 threads = 8 warps (4m x 2n),
//  warp tile 32x32.  Stage = A 8KB + 2x4KB B = 16KB; 5 stages, cp_wait<3>.
#define STAGES 5
#define STAGE_BYTES 16384

template <bool OUT_BF16, int WL>
__global__ __launch_bounds__(256, 2)
void spike_mma_gemm(const __nv_bfloat16* __restrict__ A,
                    const __nv_bfloat16* __restrict__ Wl, size_t limbStride,
                    const float* __restrict__ colbound,
                    void* __restrict__ Cout, int K, int Nout)
{
    extern __shared__ char smem[];
    const int tid  = threadIdx.x;
    const int lane = tid & 31;
    const int wid  = tid >> 5;
    const int wm   = wid & 3;       // warp row (32 rows)
    const int wn   = wid >> 2;      // warp col (32 cols)
    const int rowBase = blockIdx.x * 128;   // M-fast grid: W slab stays in L2
    const int colBase = blockIdx.y * 64;

    const int rL  = lane & 15;
    const int ccL = lane >> 4;

    float acc[2][2][4][4];          // [limb][mt][n8-tile][frag]
#pragma unroll
    for (int l = 0; l < 2; l++)
#pragma unroll
        for (int i = 0; i < 2; i++)
#pragma unroll
            for (int j = 0; j < 4; j++)
#pragma unroll
                for (int k = 0; k < 4; k++) acc[l][i][j][k] = 0.0f;

    const uint32_t smem_base = smem_u32(smem);
    const int ITERS = K / 32;

    auto load_stage = [&](int it) {
        const int s  = it % STAGES;
        const int kt = it * 32;
        const uint32_t stA = smem_base + s * STAGE_BYTES;
        const uint32_t stB = stA + 8192;
        // A: 128 rows x 64B = 512 chunks of 16B
#pragma unroll
        for (int i = 0; i < 2; i++) {
            const int idx = tid + i * 256;
            const int r = idx >> 2, c = idx & 3;
            const uint32_t d = stA + r * 64 + (((c ^ (r & 3)) << 4));
            cp_async16(d, A + (size_t)(rowBase + r) * K + kt + c * 8, 16);
        }
        // B: 2 limbs x 64 rows x 64B = 512 chunks
#pragma unroll
        for (int j = 0; j < 2; j++) {
            const int idx = tid + j * 256;
            const int limb = idx >> 8, rem = idx & 255;
            const int r = rem >> 2, c = rem & 3;
            const int gn = colBase + r;
            const int ok = (gn < Nout);
            const int gns = ok ? gn : (Nout - 1);
            const uint32_t d = stB + limb * 4096 + r * 64 + (((c ^ (r & 3)) << 4));
            cp_async16(d, Wl + (size_t)limb * limbStride + (size_t)gns * K + kt + c * 8,
                       ok ? 16 : 0);
        }
        cp_commit();
    };

    load_stage(0);
    load_stage(1);
    load_stage(2);
    load_stage(3);

    for (int it = 0; it < ITERS; ++it) {
        cp_wait<3>();
        __syncthreads();
        if (it + 4 < ITERS) load_stage(it + 4);

        const int s = it % STAGES;
        const uint32_t stA = smem_base + s * STAGE_BYTES;
        const uint32_t stB = stA + 8192;

#pragma unroll
        for (int ks = 0; ks < 2; ks++) {    // two k16 steps per 64B row
            uint32_t afr[2][4];
#pragma unroll
            for (int mt = 0; mt < 2; mt++) {
                const int row = wm * 32 + mt * 16 + rL;
                const uint32_t ad = stA + row * 64 + (((ccL + 2 * ks) ^ (row & 3)) << 4);
                ldm_x4(afr[mt], ad);
            }
#pragma unroll
            for (int limb = 0; limb < 2; limb++) {
                uint32_t bfr[2][4];
#pragma unroll
                for (int nb = 0; nb < 2; nb++) {
                    const int row = wn * 32 + nb * 16 + rL;
                    const uint32_t bd = stB + limb * 4096 + row * 64 +
                                        (((ccL + 2 * ks) ^ (row & 3)) << 4);
                    ldm_x4(bfr[nb], bd);
                }
#pragma unroll
                for (int mt = 0; mt < 2; mt++)
#pragma unroll
                    for (int nb = 0; nb < 2; nb++) {
                        mma_bf16(acc[limb][mt][nb * 2 + 0], afr[mt], bfr[nb][0], bfr[nb][2]);
                        mma_bf16(acc[limb][mt][nb * 2 + 1], afr[mt], bfr[nb][1], bfr[nb][3]);
                    }
            }
        }
    }

    // ---- epilogue: combine limbs, threshold, store (+ worklist) ----
    const int g = lane >> 2;
    const int t = lane & 3;
#pragma unroll
    for (int mt = 0; mt < 2; mt++) {
#pragma unroll
        for (int nt = 0; nt < 4; nt++) {
            const int row = rowBase + wm * 32 + mt * 16 + g;
            const int col = colBase + wn * 32 + nt * 8 + 2 * t;
            if (col >= Nout) continue;
            const float* a0 = acc[0][mt][nt];
            const float* a1 = acc[1][mt][nt];
            float v[4];
#pragma unroll
            for (int k = 0; k < 4; k++) v[k] = a0[k] + a1[k];

            if (WL != 0) {
                const float b0 = colbound[col]     + 3e-5f;
                const float b1 = colbound[col + 1] + 3e-5f;
                const unsigned base0 = (unsigned)row * (unsigned)Nout + col;
                const unsigned base1 = (unsigned)(row + 8) * (unsigned)Nout + col;
                int* cntp = &g_cnt[WL - 1];
                unsigned* listp = (WL == 1) ? g_list1 : g_list2;
                const int cap = (WL == 1) ? WL1_CAP : WL2_CAP;
                if (fabsf(v[0] - 1.0f) < b0) { int p = atomicAdd(cntp, 1); if (p < cap) listp[p] = base0; }
                if (fabsf(v[1] - 1.0f) < b1) { int p = atomicAdd(cntp, 1); if (p < cap) listp[p] = base0 + 1; }
                if (fabsf(v[2] - 1.0f) < b0) { int p = atomicAdd(cntp, 1); if (p < cap) listp[p] = base1; }
                if (fabsf(v[3] - 1.0f) < b1) { int p = atomicAdd(cntp, 1); if (p < cap) listp[p] = base1 + 1; }
            }
            if (OUT_BF16) {
                __nv_bfloat16* o = (__nv_bfloat16*)Cout;
                *reinterpret_cast<__nv_bfloat162*>(o + (size_t)row * Nout + col) =
                    __nv_bfloat162(__float2bfloat16(v[0] >= 1.0f ? 1.0f : 0.0f),
                                   __float2bfloat16(v[1] >= 1.0f ? 1.0f : 0.0f));
                *reinterpret_cast<__nv_bfloat162*>(o + (size_t)(row + 8) * Nout + col) =
                    __nv_bfloat162(__float2bfloat16(v[2] >= 1.0f ? 1.0f : 0.0f),
                                   __float2bfloat16(v[3] >= 1.0f ? 1.0f : 0.0f));
            } else {
                float* o = (float*)Cout;
                *reinterpret_cast<float2*>(o + (size_t)row * Nout + col) =
                    make_float2(v[0] >= 1.0f ? 1.0f : 0.0f, v[1] >= 1.0f ? 1.0f : 0.0f);
                *reinterpret_cast<float2*>(o + (size_t)(row + 8) * Nout + col) =
                    make_float2(v[2] >= 1.0f ? 1.0f : 0.0f, v[3] >= 1.0f ? 1.0f : 0.0f);
            }
        }
    }
}

// ---------------- host launcher ----------------
extern "C" void kernel_launch(void* const* d_in, const int* in_sizes, int n_in,
                              void* d_out, int out_size)
{
    const float* x  = (const float*)d_in[0];  // [4096, 3136] binary
    const float* W1 = (const float*)d_in[1];  // [6272, 3136]
    const float* W2 = (const float*)d_in[2];  // [500, 6272]
    float* out = (float*)d_out;               // [4096, 500]

    __nv_bfloat16 *xb, *s1b, *w1l, *w2l;
    float *cb1, *cb2; int* cnt;
    cudaGetSymbolAddress((void**)&xb,  g_xb);
    cudaGetSymbolAddress((void**)&s1b, g_s1b);
    cudaGetSymbolAddress((void**)&w1l, g_w1l);
    cudaGetSymbolAddress((void**)&w2l, g_w2l);
    cudaGetSymbolAddress((void**)&cb1, g_cb1);
    cudaGetSymbolAddress((void**)&cb2, g_cb2);
    cudaGetSymbolAddress((void**)&cnt, g_cnt);

    cudaMemsetAsync(cnt, 0, 2 * sizeof(int));
    cudaMemsetAsync(cb1, 0, FEAT_DIM * sizeof(float));
    cudaMemsetAsync(cb2, 0, 512 * sizeof(float));

    // converters (+ fused residual bounds)
    {
        int n4 = (B_DIM * IN_DIM) / 4;
        conv_bf16_kernel<<<(n4 + 255) / 256, 256>>>(
            (const float4*)x, (__nv_bfloat162*)xb, n4);
    }
    {
        size_t n = (size_t)FEAT_DIM * IN_DIM;
        int n4 = (int)(n / 4);
        split2_cb_kernel<<<(n4 + 255) / 256, 256>>>(
            (const float4*)W1, w1l, cb1, n, n4, IN_DIM);
    }
    {
        size_t n = (size_t)OUT_DIM * FEAT_DIM;
        int n4 = (int)(n / 4);
        split2_cb_kernel<<<(n4 + 255) / 256, 256>>>(
            (const float4*)W2, w2l, cb2, n, n4, FEAT_DIM);
    }

    constexpr int SMEM = STAGES * STAGE_BYTES;   // 80 KB

    // GEMM1: s1 = step(x @ W1^T)  [4096 x 6272]
    {
        cudaFuncSetAttribute(spike_mma_gemm<true, 1>,
                             cudaFuncAttributeMaxDynamicSharedMemorySize, SMEM);
        dim3 grid(B_DIM / 128, FEAT_DIM / 64);       // (32, 98) M-fast
        spike_mma_gemm<true, 1><<<grid, 256, SMEM>>>(
            xb, w1l, (size_t)FEAT_DIM * IN_DIM, cb1, (void*)s1b, IN_DIM, FEAT_DIM);
    }
    fixup1_kernel<<<256, 256>>>(x, W1, s1b);

    // GEMM2: out = step(s1 @ W2^T)  [4096 x 500]
    {
        cudaFuncSetAttribute(spike_mma_gemm<false, 2>,
                             cudaFuncAttributeMaxDynamicSharedMemorySize, SMEM);
        dim3 grid(B_DIM / 128, (OUT_DIM + 63) / 64); // (32, 8)
        spike_mma_gemm<false, 2><<<grid, 256, SMEM>>>(
            s1b, w2l, (size_t)OUT_DIM * FEAT_DIM, cb2, (void*)out, FEAT_DIM, OUT_DIM);
    }
    fixup2_kernel<<<64, 256>>>(s1b, W2, out);
}

// round 15
// speedup vs baseline: 3.0574x; 1.0405x over previous
#include <cuda_runtime.h>
#include <cuda_bf16.h>
#include <cstdint>
#include <cstddef>

#define B_DIM    4096
#define IN_DIM   3136
#define FEAT_DIM 6272
#define OUT_DIM  500
#define WL1_CAP  (1 << 20)
#define WL2_CAP  (1 << 17)

// ---------------- static device scratch (allocation-free) ----------------
__device__ __nv_bfloat16 g_xb [(size_t)B_DIM * IN_DIM];     // x as bf16 (exact)
__device__ __nv_bfloat16 g_s1b[(size_t)B_DIM * FEAT_DIM];   // hidden spikes bf16 (exact)
__device__ __nv_bfloat16 g_w1l[2ull * FEAT_DIM * IN_DIM];   // W1 limbs hi/mid
__device__ __nv_bfloat16 g_w2l[(size_t)OUT_DIM * FEAT_DIM]; // W2 hi limb only
__device__ float         g_cb1[FEAT_DIM];                   // per-col residual bound L1 (2-limb)
__device__ float         g_cb2[512];                        // per-col residual bound L2 (1-limb)
__device__ int           g_cnt[2];                          // worklist counters
__device__ unsigned      g_list1[WL1_CAP];                  // ambiguous v1 elements
__device__ unsigned      g_list2[WL2_CAP];                  // ambiguous v2 elements

// ---------------- PTX helpers ----------------
__device__ __forceinline__ uint32_t smem_u32(const void* p) {
    uint32_t a;
    asm("{ .reg .u64 t; cvta.to.shared.u64 t, %1; cvt.u32.u64 %0, t; }" : "=r"(a) : "l"(p));
    return a;
}
__device__ __forceinline__ void cp_async16(uint32_t dst, const void* src, int src_bytes) {
    asm volatile("cp.async.cg.shared.global [%0], [%1], 16, %2;"
                 :: "r"(dst), "l"(src), "r"(src_bytes) : "memory");
}
__device__ __forceinline__ void cp_commit() {
    asm volatile("cp.async.commit_group;" ::: "memory");
}
template <int N>
__device__ __forceinline__ void cp_wait() {
    asm volatile("cp.async.wait_group %0;" :: "n"(N) : "memory");
}
__device__ __forceinline__ void ldm_x4(uint32_t* r, uint32_t a) {
    asm volatile("ldmatrix.sync.aligned.m8n8.x4.shared.b16 {%0,%1,%2,%3}, [%4];"
                 : "=r"(r[0]), "=r"(r[1]), "=r"(r[2]), "=r"(r[3]) : "r"(a));
}
__device__ __forceinline__ void mma_bf16(float* c, const uint32_t* a, uint32_t b0, uint32_t b1) {
    asm volatile(
        "mma.sync.aligned.m16n8k16.row.col.f32.bf16.bf16.f32 "
        "{%0,%1,%2,%3}, {%4,%5,%6,%7}, {%8,%9}, {%0,%1,%2,%3};"
        : "+f"(c[0]), "+f"(c[1]), "+f"(c[2]), "+f"(c[3])
        : "r"(a[0]), "r"(a[1]), "r"(a[2]), "r"(a[3]), "r"(b0), "r"(b1));
}

// ---------------- converter kernels ----------------
__global__ void conv_bf16_kernel(const float4* __restrict__ in,
                                 __nv_bfloat162* __restrict__ out, int n4) {
    int i = blockIdx.x * blockDim.x + threadIdx.x;
    if (i < n4) {
        float4 v = in[i];
        out[i * 2 + 0] = __nv_bfloat162(__float2bfloat16_rn(v.x), __float2bfloat16_rn(v.y));
        out[i * 2 + 1] = __nv_bfloat162(__float2bfloat16_rn(v.z), __float2bfloat16_rn(v.w));
    }
}

// 2-limb split (hi+mid) fused with per-row residual-bound accumulation
__global__ void split2_cb_kernel(const float4* __restrict__ in,
                                 __nv_bfloat16* __restrict__ limbs,
                                 float* __restrict__ cb,
                                 size_t n, int n4, int K) {
    int i = blockIdx.x * blockDim.x + threadIdx.x;
    if (i >= n4) return;
    float4 v = in[i];
    float w[4] = {v.x, v.y, v.z, v.w};
    __nv_bfloat16 hi[4], mi[4];
    float rsum = 0.0f;
#pragma unroll
    for (int j = 0; j < 4; j++) {
        float f = w[j];
        hi[j] = __float2bfloat16_rn(f);
        float r1 = f - __bfloat162float(hi[j]);
        mi[j] = __float2bfloat16_rn(r1);
        rsum += fabsf(r1 - __bfloat162float(mi[j]));
    }
    __nv_bfloat162* o0 = reinterpret_cast<__nv_bfloat162*>(limbs);
    __nv_bfloat162* o1 = reinterpret_cast<__nv_bfloat162*>(limbs + n);
    o0[i * 2 + 0] = __nv_bfloat162(hi[0], hi[1]); o0[i * 2 + 1] = __nv_bfloat162(hi[2], hi[3]);
    o1[i * 2 + 0] = __nv_bfloat162(mi[0], mi[1]); o1[i * 2 + 1] = __nv_bfloat162(mi[2], mi[3]);

    const int row = (int)(((size_t)i * 4) / (size_t)K);
    const int first = __shfl_sync(0xFFFFFFFFu, row, 0);
    const int last  = __shfl_sync(0xFFFFFFFFu, row, 31);
    if (first == last) {
        float s = rsum;
#pragma unroll
        for (int o = 16; o; o >>= 1) s += __shfl_xor_sync(0xFFFFFFFFu, s, o);
        if ((threadIdx.x & 31) == 0) atomicAdd(&cb[row], s);
    } else {
        atomicAdd(&cb[row], rsum);
    }
}

// 1-limb split (hi only) + per-row 1-limb residual bound (for GEMM2)
__global__ void split1_cb_kernel(const float4* __restrict__ in,
                                 __nv_bfloat16* __restrict__ limb,
                                 float* __restrict__ cb, int n4, int K) {
    int i = blockIdx.x * blockDim.x + threadIdx.x;
    if (i >= n4) return;
    float4 v = in[i];
    float w[4] = {v.x, v.y, v.z, v.w};
    __nv_bfloat16 hi[4];
    float rsum = 0.0f;
#pragma unroll
    for (int j = 0; j < 4; j++) {
        hi[j] = __float2bfloat16_rn(w[j]);
        rsum += fabsf(w[j] - __bfloat162float(hi[j]));
    }
    __nv_bfloat162* o0 = reinterpret_cast<__nv_bfloat162*>(limb);
    o0[i * 2 + 0] = __nv_bfloat162(hi[0], hi[1]); o0[i * 2 + 1] = __nv_bfloat162(hi[2], hi[3]);

    const int row = (int)(((size_t)i * 4) / (size_t)K);
    const int first = __shfl_sync(0xFFFFFFFFu, row, 0);
    const int last  = __shfl_sync(0xFFFFFFFFu, row, 31);
    if (first == last) {
        float s = rsum;
#pragma unroll
        for (int o = 16; o; o >>= 1) s += __shfl_xor_sync(0xFFFFFFFFu, s, o);
        if ((threadIdx.x & 31) == 0) atomicAdd(&cb[row], s);
    } else {
        atomicAdd(&cb[row], rsum);
    }
}

// exact fp32 recompute of ambiguous v1 elements -> rewrite s1 spike
__global__ void fixup1_kernel(const float* __restrict__ x, const float* __restrict__ W1,
                              __nv_bfloat16* __restrict__ s1b) {
    const int warp = (blockIdx.x * blockDim.x + threadIdx.x) >> 5;
    const int lane = threadIdx.x & 31;
    const int nwarp = (gridDim.x * blockDim.x) >> 5;
    int cnt = g_cnt[0]; if (cnt > WL1_CAP) cnt = WL1_CAP;
    for (int w = warp; w < cnt; w += nwarp) {
        const unsigned idx = g_list1[w];
        const int b = idx / FEAT_DIM, j = idx % FEAT_DIM;
        const float* xr = x  + (size_t)b * IN_DIM;
        const float* wr = W1 + (size_t)j * IN_DIM;
        float s = 0.0f;
        for (int i = lane; i < IN_DIM; i += 32) s = fmaf(xr[i], wr[i], s);
#pragma unroll
        for (int o = 16; o; o >>= 1) s += __shfl_xor_sync(0xFFFFFFFFu, s, o);
        if (lane == 0)
            s1b[(size_t)b * FEAT_DIM + j] = __float2bfloat16(s >= 1.0f ? 1.0f : 0.0f);
    }
}

// exact fp32 recompute of ambiguous v2 elements -> rewrite output spike
__global__ void fixup2_kernel(const __nv_bfloat16* __restrict__ s1b,
                              const float* __restrict__ W2, float* __restrict__ out) {
    const int warp = (blockIdx.x * blockDim.x + threadIdx.x) >> 5;
    const int lane = threadIdx.x & 31;
    const int nwarp = (gridDim.x * blockDim.x) >> 5;
    int cnt = g_cnt[1]; if (cnt > WL2_CAP) cnt = WL2_CAP;
    for (int w = warp; w < cnt; w += nwarp) {
        const unsigned idx = g_list2[w];
        const int b = idx / OUT_DIM, j = idx % OUT_DIM;
        const __nv_bfloat16* sr = s1b + (size_t)b * FEAT_DIM;
        const float* wr = W2 + (size_t)j * FEAT_DIM;
        float s = 0.0f;
        for (int i = lane; i < FEAT_DIM; i += 32)
            s = fmaf(__bfloat162float(sr[i]), wr[i], s);
#pragma unroll
        for (int o = 16; o; o >>= 1) s += __shfl_xor_sync(0xFFFFFFFFu, s, o);
        if (lane == 0)
            out[(size_t)b * OUT_DIM + j] = (s >= 1.0f) ? 1.0f : 0.0f;
    }
}

// ---------------- fused mma.sync spike GEMM ----------------
//  C[M,Nout] = step( A[M,K] @ W[Nout,K]^T ), W as NL bf16 limbs (shared acc).
//  128x128 CTA tile, BK=32, 256 threads = 8 warps (4m x 2n), warp tile 32x64.
//  WL != 0: push |v-1| < colbound[col]+slack to worklist WL for exact fixup.
#define STAGES 4

template <int NL, bool OUT_BF16, int WL>
__global__ __launch_bounds__(256, 2)
void spike_mma_gemm(const __nv_bfloat16* __restrict__ A,
                    const __nv_bfloat16* __restrict__ Wl, size_t limbStride,
                    const float* __restrict__ colbound,
                    void* __restrict__ Cout, int K, int Nout)
{
    constexpr int STAGE_BYTES = (1 + NL) * 128 * 64;

    extern __shared__ char smem[];
    const int tid  = threadIdx.x;
    const int lane = tid & 31;
    const int wid  = tid >> 5;
    const int wm   = wid & 3;
    const int wn   = wid >> 2;
    const int rowBase = blockIdx.x * 128;   // M-fast grid: W slab reused in L2
    const int colBase = blockIdx.y * 128;

    const int rL  = lane & 15;
    const int ccL = lane >> 4;

    float acc[2][8][4];
#pragma unroll
    for (int i = 0; i < 2; i++)
#pragma unroll
        for (int j = 0; j < 8; j++)
#pragma unroll
            for (int k = 0; k < 4; k++) acc[i][j][k] = 0.0f;

    const uint32_t smem_base = smem_u32(smem);
    const int ITERS = K / 32;

    auto load_stage = [&](int it) {
        const int s  = it % STAGES;
        const int kt = it * 32;
        const uint32_t stA = smem_base + s * STAGE_BYTES;
        const uint32_t stB = stA + 128 * 64;
#pragma unroll
        for (int i = 0; i < 2; i++) {
            const int idx = tid * 2 + i;            // 0..511
            const int r = idx >> 2, c = idx & 3;
            const uint32_t d = stA + r * 64 + (((c ^ (r & 3)) << 4));
            cp_async16(d, A + (size_t)(rowBase + r) * K + kt + c * 8, 16);
        }
#pragma unroll
        for (int j = 0; j < 2 * NL; j++) {
            const int idx = tid + j * 256;          // 0..NL*512-1
            const int limb = idx >> 9, rem = idx & 511;
            const int r = rem >> 2, c = rem & 3;
            const int gn = colBase + r;
            const int ok = (gn < Nout);
            const int gns = ok ? gn : (Nout - 1);
            const uint32_t d = stB + limb * 8192 + r * 64 + (((c ^ (r & 3)) << 4));
            cp_async16(d, Wl + (size_t)limb * limbStride + (size_t)gns * K + kt + c * 8,
                       ok ? 16 : 0);
        }
        cp_commit();
    };

    load_stage(0);
    load_stage(1);
    load_stage(2);

    for (int it = 0; it < ITERS; ++it) {
        cp_wait<2>();
        __syncthreads();
        if (it + 3 < ITERS) load_stage(it + 3);

        const int s = it % STAGES;
        const uint32_t stA = smem_base + s * STAGE_BYTES;
        const uint32_t stB = stA + 128 * 64;

#pragma unroll
        for (int ks = 0; ks < 2; ks++) {
            uint32_t afr[2][4];
#pragma unroll
            for (int mt = 0; mt < 2; mt++) {
                const int row = wm * 32 + mt * 16 + rL;
                const uint32_t ad = stA + row * 64 + (((ccL + 2 * ks) ^ (row & 3)) << 4);
                ldm_x4(afr[mt], ad);
            }
#pragma unroll
            for (int limb = 0; limb < NL; limb++) {
                uint32_t bfr[4][4];
#pragma unroll
                for (int nb = 0; nb < 4; nb++) {
                    const int row = wn * 64 + nb * 16 + rL;
                    const uint32_t bd = stB + limb * 8192 + row * 64 +
                                        (((ccL + 2 * ks) ^ (row & 3)) << 4);
                    ldm_x4(bfr[nb], bd);
                }
#pragma unroll
                for (int mt = 0; mt < 2; mt++)
#pragma unroll
                    for (int nb = 0; nb < 4; nb++) {
                        mma_bf16(acc[mt][nb * 2 + 0], afr[mt], bfr[nb][0], bfr[nb][2]);
                        mma_bf16(acc[mt][nb * 2 + 1], afr[mt], bfr[nb][1], bfr[nb][3]);
                    }
            }
        }
    }

    // ---- epilogue: threshold + stores (+ ambiguity worklist when WL) ----
    const int g = lane >> 2;
    const int t = lane & 3;
#pragma unroll
    for (int mt = 0; mt < 2; mt++) {
#pragma unroll
        for (int nt = 0; nt < 8; nt++) {
            const float* c = acc[mt][nt];
            const int row = rowBase + wm * 32 + mt * 16 + g;
            const int col = colBase + wn * 64 + nt * 8 + 2 * t;
            if (WL != 0 && col < Nout) {
                const float b0 = colbound[col]     + 3e-5f;
                const float b1 = colbound[col + 1] + 3e-5f;
                const float m[4] = {fabsf(c[0] - 1.0f), fabsf(c[1] - 1.0f),
                                    fabsf(c[2] - 1.0f), fabsf(c[3] - 1.0f)};
                const unsigned base0 = (unsigned)row * (unsigned)Nout + col;
                const unsigned base1 = (unsigned)(row + 8) * (unsigned)Nout + col;
                int* cntp = &g_cnt[WL - 1];
                unsigned* listp = (WL == 1) ? g_list1 : g_list2;
                const int cap = (WL == 1) ? WL1_CAP : WL2_CAP;
                if (m[0] < b0) { int p = atomicAdd(cntp, 1); if (p < cap) listp[p] = base0; }
                if (m[1] < b1) { int p = atomicAdd(cntp, 1); if (p < cap) listp[p] = base0 + 1; }
                if (m[2] < b0) { int p = atomicAdd(cntp, 1); if (p < cap) listp[p] = base1; }
                if (m[3] < b1) { int p = atomicAdd(cntp, 1); if (p < cap) listp[p] = base1 + 1; }
            }
            if (OUT_BF16) {
                __nv_bfloat16* o = (__nv_bfloat16*)Cout;
                __nv_bfloat162 v0(__float2bfloat16(c[0] >= 1.0f ? 1.0f : 0.0f),
                                  __float2bfloat16(c[1] >= 1.0f ? 1.0f : 0.0f));
                __nv_bfloat162 v1(__float2bfloat16(c[2] >= 1.0f ? 1.0f : 0.0f),
                                  __float2bfloat16(c[3] >= 1.0f ? 1.0f : 0.0f));
                *reinterpret_cast<__nv_bfloat162*>(o + (size_t)row * Nout + col) = v0;
                *reinterpret_cast<__nv_bfloat162*>(o + (size_t)(row + 8) * Nout + col) = v1;
            } else {
                float* o = (float*)Cout;
                if (col < Nout) {
                    float2 v0 = make_float2(c[0] >= 1.0f ? 1.0f : 0.0f,
                                            c[1] >= 1.0f ? 1.0f : 0.0f);
                    float2 v1 = make_float2(c[2] >= 1.0f ? 1.0f : 0.0f,
                                            c[3] >= 1.0f ? 1.0f : 0.0f);
                    *reinterpret_cast<float2*>(o + (size_t)row * Nout + col) = v0;
                    *reinterpret_cast<float2*>(o + (size_t)(row + 8) * Nout + col) = v1;
                }
            }
        }
    }
}

// ---------------- host launcher ----------------
extern "C" void kernel_launch(void* const* d_in, const int* in_sizes, int n_in,
                              void* d_out, int out_size)
{
    const float* x  = (const float*)d_in[0];  // [4096, 3136] binary
    const float* W1 = (const float*)d_in[1];  // [6272, 3136]
    const float* W2 = (const float*)d_in[2];  // [500, 6272]
    float* out = (float*)d_out;               // [4096, 500]

    __nv_bfloat16 *xb, *s1b, *w1l, *w2l;
    float *cb1, *cb2; int* cnt;
    cudaGetSymbolAddress((void**)&xb,  g_xb);
    cudaGetSymbolAddress((void**)&s1b, g_s1b);
    cudaGetSymbolAddress((void**)&w1l, g_w1l);
    cudaGetSymbolAddress((void**)&w2l, g_w2l);
    cudaGetSymbolAddress((void**)&cb1, g_cb1);
    cudaGetSymbolAddress((void**)&cb2, g_cb2);
    cudaGetSymbolAddress((void**)&cnt, g_cnt);

    cudaMemsetAsync(cnt, 0, 2 * sizeof(int));
    cudaMemsetAsync(cb1, 0, FEAT_DIM * sizeof(float));
    cudaMemsetAsync(cb2, 0, 512 * sizeof(float));

    // converters (+ fused residual bounds)
    {
        int n4 = (B_DIM * IN_DIM) / 4;
        conv_bf16_kernel<<<(n4 + 255) / 256, 256>>>(
            (const float4*)x, (__nv_bfloat162*)xb, n4);
    }
    {
        size_t n = (size_t)FEAT_DIM * IN_DIM;
        int n4 = (int)(n / 4);
        split2_cb_kernel<<<(n4 + 255) / 256, 256>>>(
            (const float4*)W1, w1l, cb1, n, n4, IN_DIM);
    }
    {
        int n4 = (int)(((size_t)OUT_DIM * FEAT_DIM) / 4);
        split1_cb_kernel<<<(n4 + 255) / 256, 256>>>(
            (const float4*)W2, w2l, cb2, n4, FEAT_DIM);
    }

    // GEMM1: s1 = step(x @ W1^T), 2-limb + certified fixup. [4096 x 6272]
    {
        constexpr int SMEM = STAGES * 3 * 128 * 64;   // 96 KB
        cudaFuncSetAttribute(spike_mma_gemm<2, true, 1>,
                             cudaFuncAttributeMaxDynamicSharedMemorySize, SMEM);
        dim3 grid(B_DIM / 128, FEAT_DIM / 128);       // (32, 49) M-fast
        spike_mma_gemm<2, true, 1><<<grid, 256, SMEM>>>(
            xb, w1l, (size_t)FEAT_DIM * IN_DIM, cb1, (void*)s1b, IN_DIM, FEAT_DIM);
    }
    // exact fp32 fixup of ambiguous hidden elements
    fixup1_kernel<<<296, 256>>>(x, W1, s1b);

    // GEMM2: out = step(s1 @ W2^T), 1-limb + certified fixup. [4096 x 500]
    {
        constexpr int SMEM = STAGES * 2 * 128 * 64;   // 64 KB
        cudaFuncSetAttribute(spike_mma_gemm<1, false, 2>,
                             cudaFuncAttributeMaxDynamicSharedMemorySize, SMEM);
        dim3 grid(B_DIM / 128, (OUT_DIM + 127) / 128);  // (32, 4)
        spike_mma_gemm<1, false, 2><<<grid, 256, SMEM>>>(
            s1b, w2l, (size_t)OUT_DIM * FEAT_DIM, cb2, (void*)out, FEAT_DIM, OUT_DIM);
    }
    // exact fp32 fixup of ambiguous output elements
    fixup2_kernel<<<64, 256>>>(s1b, W2, out);
}

// round 16
// speedup vs baseline: 3.7256x; 1.2186x over previous
#include <cuda_runtime.h>
#include <cuda_fp16.h>
#include <cuda_bf16.h>
#include <cstdint>
#include <cstddef>

#define B_DIM    4096
#define IN_DIM   3136
#define FEAT_DIM 6272
#define OUT_DIM  500
#define WL1_CAP  (1 << 20)
#define WL2_CAP  (1 << 17)

// ---------------- static device scratch (allocation-free) ----------------
__device__ __half         g_xh [(size_t)B_DIM * IN_DIM];     // x as fp16 (exact)
__device__ __half         g_s1h[(size_t)B_DIM * FEAT_DIM];   // hidden spikes fp16 (exact)
__device__ __half         g_w1h[(size_t)FEAT_DIM * IN_DIM];  // W1 hi limb (fp16)
__device__ __nv_bfloat16  g_w1m[(size_t)FEAT_DIM * IN_DIM];  // W1 mid limb (bf16 of residual)
__device__ __half         g_w2h[(size_t)OUT_DIM * FEAT_DIM]; // W2 hi limb (fp16)
__device__ float          g_cb1h[FEAT_DIM];                  // Σ|w-hi|       (L1 cert)
__device__ float          g_cb1m[FEAT_DIM];                  // Σ|w-hi-mid|   (L1 level-2 cert)
__device__ float          g_cb2[512];                        // Σ|w-hi|       (L2 cert)
__device__ int            g_cnt[2];                          // worklist counters
__device__ unsigned       g_list1[WL1_CAP];                  // ambiguous v1 idx
__device__ float          g_val1 [WL1_CAP];                  // ambiguous v1 value (hi GEMM)
__device__ unsigned       g_list2[WL2_CAP];                  // ambiguous v2 idx

// ---------------- PTX helpers ----------------
__device__ __forceinline__ uint32_t smem_u32(const void* p) {
    uint32_t a;
    asm("{ .reg .u64 t; cvta.to.shared.u64 t, %1; cvt.u32.u64 %0, t; }" : "=r"(a) : "l"(p));
    return a;
}
__device__ __forceinline__ void cp_async16(uint32_t dst, const void* src, int src_bytes) {
    asm volatile("cp.async.cg.shared.global [%0], [%1], 16, %2;"
                 :: "r"(dst), "l"(src), "r"(src_bytes) : "memory");
}
__device__ __forceinline__ void cp_commit() {
    asm volatile("cp.async.commit_group;" ::: "memory");
}
template <int N>
__device__ __forceinline__ void cp_wait() {
    asm volatile("cp.async.wait_group %0;" :: "n"(N) : "memory");
}
__device__ __forceinline__ void ldm_x4(uint32_t* r, uint32_t a) {
    asm volatile("ldmatrix.sync.aligned.m8n8.x4.shared.b16 {%0,%1,%2,%3}, [%4];"
                 : "=r"(r[0]), "=r"(r[1]), "=r"(r[2]), "=r"(r[3]) : "r"(a));
}
__device__ __forceinline__ void mma_f16(float* c, const uint32_t* a, uint32_t b0, uint32_t b1) {
    asm volatile(
        "mma.sync.aligned.m16n8k16.row.col.f32.f16.f16.f32 "
        "{%0,%1,%2,%3}, {%4,%5,%6,%7}, {%8,%9}, {%0,%1,%2,%3};"
        : "+f"(c[0]), "+f"(c[1]), "+f"(c[2]), "+f"(c[3])
        : "r"(a[0]), "r"(a[1]), "r"(a[2]), "r"(a[3]), "r"(b0), "r"(b1));
}

// warp-aggregated worklist push; ALL 32 lanes must call (uniform path)
__device__ __forceinline__ void wl_push(int* cntp, unsigned* listp, float* valp,
                                        int cap, bool need, unsigned idx, float v) {
    const unsigned mask = __ballot_sync(0xFFFFFFFFu, need);
    if (!mask) return;
    const int lane = threadIdx.x & 31;
    const int leader = __ffs(mask) - 1;
    int base = 0;
    if (lane == leader) base = atomicAdd(cntp, __popc(mask));
    base = __shfl_sync(0xFFFFFFFFu, base, leader);
    const int off = __popc(mask & ((1u << lane) - 1));
    if (need && (base + off) < cap) {
        listp[base + off] = idx;
        if (valp) valp[base + off] = v;
    }
}

// ---------------- converter kernels ----------------
__global__ void conv_f16_kernel(const float4* __restrict__ in,
                                __half2* __restrict__ out, int n4) {
    int i = blockIdx.x * blockDim.x + threadIdx.x;
    if (i < n4) {
        float4 v = in[i];
        out[i * 2 + 0] = __halves2half2(__float2half_rn(v.x), __float2half_rn(v.y));
        out[i * 2 + 1] = __halves2half2(__float2half_rn(v.z), __float2half_rn(v.w));
    }
}

// W1: hi fp16 + mid bf16(residual) + two per-row bounds
__global__ void split_w1_kernel(const float4* __restrict__ in,
                                __half* __restrict__ hiArr,
                                __nv_bfloat16* __restrict__ midArr,
                                float* __restrict__ cbh, float* __restrict__ cbm,
                                int n4, int K) {
    int i = blockIdx.x * blockDim.x + threadIdx.x;
    if (i >= n4) return;
    float4 v = in[i];
    float w[4] = {v.x, v.y, v.z, v.w};
    __half hi[4]; __nv_bfloat16 mi[4];
    float sh = 0.0f, sm = 0.0f;
#pragma unroll
    for (int j = 0; j < 4; j++) {
        float f = w[j];
        hi[j] = __float2half_rn(f);
        float r1 = f - __half2float(hi[j]);
        sh += fabsf(r1);
        mi[j] = __float2bfloat16_rn(r1);
        sm += fabsf(r1 - __bfloat162float(mi[j]));
    }
    reinterpret_cast<__half2*>(hiArr)[i * 2 + 0] = __halves2half2(hi[0], hi[1]);
    reinterpret_cast<__half2*>(hiArr)[i * 2 + 1] = __halves2half2(hi[2], hi[3]);
    reinterpret_cast<__nv_bfloat162*>(midArr)[i * 2 + 0] = __nv_bfloat162(mi[0], mi[1]);
    reinterpret_cast<__nv_bfloat162*>(midArr)[i * 2 + 1] = __nv_bfloat162(mi[2], mi[3]);

    const int row = (int)(((size_t)i * 4) / (size_t)K);
    const int first = __shfl_sync(0xFFFFFFFFu, row, 0);
    const int last  = __shfl_sync(0xFFFFFFFFu, row, 31);
    if (first == last) {
#pragma unroll
        for (int o = 16; o; o >>= 1) {
            sh += __shfl_xor_sync(0xFFFFFFFFu, sh, o);
            sm += __shfl_xor_sync(0xFFFFFFFFu, sm, o);
        }
        if ((threadIdx.x & 31) == 0) { atomicAdd(&cbh[row], sh); atomicAdd(&cbm[row], sm); }
    } else {
        atomicAdd(&cbh[row], sh);
        atomicAdd(&cbm[row], sm);
    }
}

// W2: hi fp16 + per-row bound
__global__ void split_w2_kernel(const float4* __restrict__ in,
                                __half* __restrict__ hiArr,
                                float* __restrict__ cb, int n4, int K) {
    int i = blockIdx.x * blockDim.x + threadIdx.x;
    if (i >= n4) return;
    float4 v = in[i];
    float w[4] = {v.x, v.y, v.z, v.w};
    __half hi[4];
    float s = 0.0f;
#pragma unroll
    for (int j = 0; j < 4; j++) {
        hi[j] = __float2half_rn(w[j]);
        s += fabsf(w[j] - __half2float(hi[j]));
    }
    reinterpret_cast<__half2*>(hiArr)[i * 2 + 0] = __halves2half2(hi[0], hi[1]);
    reinterpret_cast<__half2*>(hiArr)[i * 2 + 1] = __halves2half2(hi[2], hi[3]);

    const int row = (int)(((size_t)i * 4) / (size_t)K);
    const int first = __shfl_sync(0xFFFFFFFFu, row, 0);
    const int last  = __shfl_sync(0xFFFFFFFFu, row, 31);
    if (first == last) {
#pragma unroll
        for (int o = 16; o; o >>= 1) s += __shfl_xor_sync(0xFFFFFFFFu, s, o);
        if ((threadIdx.x & 31) == 0) atomicAdd(&cb[row], s);
    } else {
        atomicAdd(&cb[row], s);
    }
}

// two-level fixup of ambiguous v1 elements: bf16 mid correction, then (rarely)
// full exact fp32 re-dot. One warp per item.
__global__ void fixup1_kernel(const __half* __restrict__ xh,
                              const __nv_bfloat16* __restrict__ w1m,
                              const float* __restrict__ x,
                              const float* __restrict__ W1,
                              __half* __restrict__ s1h) {
    const int warp = (blockIdx.x * blockDim.x + threadIdx.x) >> 5;
    const int lane = threadIdx.x & 31;
    const int nwarp = (gridDim.x * blockDim.x) >> 5;
    int cnt = g_cnt[0]; if (cnt > WL1_CAP) cnt = WL1_CAP;
    for (int w = warp; w < cnt; w += nwarp) {
        const unsigned idx = g_list1[w];
        const int b = idx / FEAT_DIM, j = idx % FEAT_DIM;
        // level 1: v_hi + exact-ish mid correction
        const __half* xr = xh + (size_t)b * IN_DIM;
        const __nv_bfloat16* mr = w1m + (size_t)j * IN_DIM;
        float corr = 0.0f;
        for (int i = lane; i < IN_DIM; i += 32)
            corr = fmaf(__half2float(xr[i]), __bfloat162float(mr[i]), corr);
#pragma unroll
        for (int o = 16; o; o >>= 1) corr += __shfl_xor_sync(0xFFFFFFFFu, corr, o);
        float vv = g_val1[w] + corr;      // uniform across warp after reduction
        // level 2: exact fp32 recompute if still ambiguous
        if (fabsf(vv - 1.0f) < g_cb1m[j] + 2e-5f) {
            const float* xf = x  + (size_t)b * IN_DIM;
            const float* wf = W1 + (size_t)j * IN_DIM;
            float s = 0.0f;
            for (int i = lane; i < IN_DIM; i += 32) s = fmaf(xf[i], wf[i], s);
#pragma unroll
            for (int o = 16; o; o >>= 1) s += __shfl_xor_sync(0xFFFFFFFFu, s, o);
            vv = s;
        }
        if (lane == 0)
            s1h[(size_t)b * FEAT_DIM + j] = __float2half(vv >= 1.0f ? 1.0f : 0.0f);
    }
}

// exact fp32 recompute of ambiguous v2 elements -> rewrite output spike
__global__ void fixup2_kernel(const __half* __restrict__ s1h,
                              const float* __restrict__ W2, float* __restrict__ out) {
    const int warp = (blockIdx.x * blockDim.x + threadIdx.x) >> 5;
    const int lane = threadIdx.x & 31;
    const int nwarp = (gridDim.x * blockDim.x) >> 5;
    int cnt = g_cnt[1]; if (cnt > WL2_CAP) cnt = WL2_CAP;
    for (int w = warp; w < cnt; w += nwarp) {
        const unsigned idx = g_list2[w];
        const int b = idx / OUT_DIM, j = idx % OUT_DIM;
        const __half* sr = s1h + (size_t)b * FEAT_DIM;
        const float* wr = W2 + (size_t)j * FEAT_DIM;
        float s = 0.0f;
        for (int i = lane; i < FEAT_DIM; i += 32)
            s = fmaf(__half2float(sr[i]), wr[i], s);
#pragma unroll
        for (int o = 16; o; o >>= 1) s += __shfl_xor_sync(0xFFFFFFFFu, s, o);
        if (lane == 0)
            out[(size_t)b * OUT_DIM + j] = (s >= 1.0f) ? 1.0f : 0.0f;
    }
}

// ---------------- fused fp16 mma.sync spike GEMM (1 hi limb) ----------------
//  C[M,Nout] = step-with-certification( A[M,K] @ Whi[Nout,K]^T )
//  128x128 CTA tile, BK=32, 256 threads = 8 warps (4m x 2n), warp tile 32x64.
//  WL=1: push (idx, value). WL=2: push idx only.
#define STAGES 4
#define STAGE_BYTES (2 * 128 * 64)

template <bool OUT_HALF, int WL>
__global__ __launch_bounds__(256, 2)
void spike_mma_gemm(const __half* __restrict__ A,
                    const __half* __restrict__ Whi,
                    const float* __restrict__ colbound,
                    void* __restrict__ Cout, int K, int Nout)
{
    extern __shared__ char smem[];
    const int tid  = threadIdx.x;
    const int lane = tid & 31;
    const int wid  = tid >> 5;
    const int wm   = wid & 3;
    const int wn   = wid >> 2;
    const int rowBase = blockIdx.x * 128;   // M-fast grid: W slab reused in L2
    const int colBase = blockIdx.y * 128;

    const int rL  = lane & 15;
    const int ccL = lane >> 4;

    float acc[2][8][4];
#pragma unroll
    for (int i = 0; i < 2; i++)
#pragma unroll
        for (int j = 0; j < 8; j++)
#pragma unroll
            for (int k = 0; k < 4; k++) acc[i][j][k] = 0.0f;

    const uint32_t smem_base = smem_u32(smem);
    const int ITERS = K / 32;

    auto load_stage = [&](int it) {
        const int s  = it % STAGES;
        const int kt = it * 32;
        const uint32_t stA = smem_base + s * STAGE_BYTES;
        const uint32_t stB = stA + 128 * 64;
#pragma unroll
        for (int i = 0; i < 2; i++) {
            const int idx = tid * 2 + i;            // 0..511
            const int r = idx >> 2, c = idx & 3;
            const uint32_t d = stA + r * 64 + (((c ^ (r & 3)) << 4));
            cp_async16(d, A + (size_t)(rowBase + r) * K + kt + c * 8, 16);
        }
#pragma unroll
        for (int j = 0; j < 2; j++) {
            const int idx = tid + j * 256;          // 0..511
            const int r = idx >> 2, c = idx & 3;
            const int gn = colBase + r;
            const int ok = (gn < Nout);
            const int gns = ok ? gn : (Nout - 1);
            const uint32_t d = stB + r * 64 + (((c ^ (r & 3)) << 4));
            cp_async16(d, Whi + (size_t)gns * K + kt + c * 8, ok ? 16 : 0);
        }
        cp_commit();
    };

    load_stage(0);
    load_stage(1);
    load_stage(2);

    for (int it = 0; it < ITERS; ++it) {
        cp_wait<2>();
        __syncthreads();
        if (it + 3 < ITERS) load_stage(it + 3);

        const int s = it % STAGES;
        const uint32_t stA = smem_base + s * STAGE_BYTES;
        const uint32_t stB = stA + 128 * 64;

#pragma unroll
        for (int ks = 0; ks < 2; ks++) {
            uint32_t afr[2][4];
#pragma unroll
            for (int mt = 0; mt < 2; mt++) {
                const int row = wm * 32 + mt * 16 + rL;
                const uint32_t ad = stA + row * 64 + (((ccL + 2 * ks) ^ (row & 3)) << 4);
                ldm_x4(afr[mt], ad);
            }
            uint32_t bfr[4][4];
#pragma unroll
            for (int nb = 0; nb < 4; nb++) {
                const int row = wn * 64 + nb * 16 + rL;
                const uint32_t bd = stB + row * 64 + (((ccL + 2 * ks) ^ (row & 3)) << 4);
                ldm_x4(bfr[nb], bd);
            }
#pragma unroll
            for (int mt = 0; mt < 2; mt++)
#pragma unroll
                for (int nb = 0; nb < 4; nb++) {
                    mma_f16(acc[mt][nb * 2 + 0], afr[mt], bfr[nb][0], bfr[nb][2]);
                    mma_f16(acc[mt][nb * 2 + 1], afr[mt], bfr[nb][1], bfr[nb][3]);
                }
        }
    }

    // ---- epilogue: certify + threshold + store ----
    const int g = lane >> 2;
    const int t = lane & 3;
    int* cntp = &g_cnt[WL - 1];
    unsigned* listp = (WL == 1) ? g_list1 : g_list2;
    float* valp = (WL == 1) ? g_val1 : nullptr;
    const int cap = (WL == 1) ? WL1_CAP : WL2_CAP;
#pragma unroll
    for (int mt = 0; mt < 2; mt++) {
#pragma unroll
        for (int nt = 0; nt < 8; nt++) {
            const float* c = acc[mt][nt];
            const int row = rowBase + wm * 32 + mt * 16 + g;
            const int col = colBase + wn * 64 + nt * 8 + 2 * t;
            const bool in0 = (col < Nout);
            const bool in1 = (col + 1 < Nout);
            const float b0 = in0 ? (colbound[col]     + 3e-5f) : 0.0f;
            const float b1 = in1 ? (colbound[col + 1] + 3e-5f) : 0.0f;
            const unsigned base0 = (unsigned)row * (unsigned)Nout + col;
            const unsigned base1 = (unsigned)(row + 8) * (unsigned)Nout + col;
            wl_push(cntp, listp, valp, cap, in0 && fabsf(c[0] - 1.0f) < b0, base0,     c[0]);
            wl_push(cntp, listp, valp, cap, in1 && fabsf(c[1] - 1.0f) < b1, base0 + 1, c[1]);
            wl_push(cntp, listp, valp, cap, in0 && fabsf(c[2] - 1.0f) < b0, base1,     c[2]);
            wl_push(cntp, listp, valp, cap, in1 && fabsf(c[3] - 1.0f) < b1, base1 + 1, c[3]);
            if (OUT_HALF) {
                __half* o = (__half*)Cout;   // Nout multiple of 2 here (6272)
                *reinterpret_cast<__half2*>(o + (size_t)row * Nout + col) =
                    __halves2half2(__float2half(c[0] >= 1.0f ? 1.0f : 0.0f),
                                   __float2half(c[1] >= 1.0f ? 1.0f : 0.0f));
                *reinterpret_cast<__half2*>(o + (size_t)(row + 8) * Nout + col) =
                    __halves2half2(__float2half(c[2] >= 1.0f ? 1.0f : 0.0f),
                                   __float2half(c[3] >= 1.0f ? 1.0f : 0.0f));
            } else {
                float* o = (float*)Cout;
                if (in0) {                   // col even, Nout even -> pair fits
                    *reinterpret_cast<float2*>(o + (size_t)row * Nout + col) =
                        make_float2(c[0] >= 1.0f ? 1.0f : 0.0f, c[1] >= 1.0f ? 1.0f : 0.0f);
                    *reinterpret_cast<float2*>(o + (size_t)(row + 8) * Nout + col) =
                        make_float2(c[2] >= 1.0f ? 1.0f : 0.0f, c[3] >= 1.0f ? 1.0f : 0.0f);
                }
            }
        }
    }
}

// ---------------- host launcher ----------------
extern "C" void kernel_launch(void* const* d_in, const int* in_sizes, int n_in,
                              void* d_out, int out_size)
{
    const float* x  = (const float*)d_in[0];  // [4096, 3136] binary
    const float* W1 = (const float*)d_in[1];  // [6272, 3136]
    const float* W2 = (const float*)d_in[2];  // [500, 6272]
    float* out = (float*)d_out;               // [4096, 500]

    __half *xh, *s1h, *w1h, *w2h;
    __nv_bfloat16* w1m;
    float *cb1h, *cb1m, *cb2; int* cnt;
    cudaGetSymbolAddress((void**)&xh,  g_xh);
    cudaGetSymbolAddress((void**)&s1h, g_s1h);
    cudaGetSymbolAddress((void**)&w1h, g_w1h);
    cudaGetSymbolAddress((void**)&w1m, g_w1m);
    cudaGetSymbolAddress((void**)&w2h, g_w2h);
    cudaGetSymbolAddress((void**)&cb1h, g_cb1h);
    cudaGetSymbolAddress((void**)&cb1m, g_cb1m);
    cudaGetSymbolAddress((void**)&cb2, g_cb2);
    cudaGetSymbolAddress((void**)&cnt, g_cnt);

    cudaMemsetAsync(cnt, 0, 2 * sizeof(int));
    cudaMemsetAsync(cb1h, 0, FEAT_DIM * sizeof(float));
    cudaMemsetAsync(cb1m, 0, FEAT_DIM * sizeof(float));
    cudaMemsetAsync(cb2, 0, 512 * sizeof(float));

    // converters (+ fused residual bounds)
    {
        int n4 = (B_DIM * IN_DIM) / 4;
        conv_f16_kernel<<<(n4 + 255) / 256, 256>>>((const float4*)x, (__half2*)xh, n4);
    }
    {
        int n4 = (int)(((size_t)FEAT_DIM * IN_DIM) / 4);
        split_w1_kernel<<<(n4 + 255) / 256, 256>>>(
            (const float4*)W1, w1h, w1m, cb1h, cb1m, n4, IN_DIM);
    }
    {
        int n4 = (int)(((size_t)OUT_DIM * FEAT_DIM) / 4);
        split_w2_kernel<<<(n4 + 255) / 256, 256>>>(
            (const float4*)W2, w2h, cb2, n4, FEAT_DIM);
    }

    constexpr int SMEM = STAGES * STAGE_BYTES;   // 64 KB

    // GEMM1: s1 = step(x @ W1hi^T) + certification. [4096 x 6272]
    {
        cudaFuncSetAttribute(spike_mma_gemm<true, 1>,
                             cudaFuncAttributeMaxDynamicSharedMemorySize, SMEM);
        dim3 grid(B_DIM / 128, FEAT_DIM / 128);       // (32, 49) M-fast
        spike_mma_gemm<true, 1><<<grid, 256, SMEM>>>(
            xh, w1h, cb1h, (void*)s1h, IN_DIM, FEAT_DIM);
    }
    // two-level fixup of ambiguous hidden elements
    fixup1_kernel<<<592, 256>>>(xh, w1m, x, W1, s1h);

    // GEMM2: out = step(s1 @ W2hi^T) + certification. [4096 x 500]
    {
        cudaFuncSetAttribute(spike_mma_gemm<false, 2>,
                             cudaFuncAttributeMaxDynamicSharedMemorySize, SMEM);
        dim3 grid(B_DIM / 128, (OUT_DIM + 127) / 128);  // (32, 4)
        spike_mma_gemm<false, 2><<<grid, 256, SMEM>>>(
            s1h, w2h, cb2, (void*)out, FEAT_DIM, OUT_DIM);
    }
    // exact fp32 fixup of ambiguous output elements
    fixup2_kernel<<<64, 256>>>(s1h, W2, out);
}